// round 13
// baseline (speedup 1.0000x reference)
#include <cuda_runtime.h>
#include <cuda_fp16.h>
#include <math.h>
#include <stdint.h>

#define B 32
#define S 512
#define D 1536
#define D24 64
#define KF 10

// ---------------- device scratch (no allocation allowed) ----------------
__device__ __half g_xh[(size_t)B * S * D];   // xn in fp16
__device__ __half g_wh[2 * S * S];           // W in fp16 (Wi, Wii)
__device__ float g_acc[B * KF];
__device__ int   g_sel[B];

__device__ __forceinline__ float gelu_f(float v) {
    return 0.5f * v * (1.0f + erff(v * 0.7071067811865476f));
}
__device__ __forceinline__ uint32_t smem_u32(const void* p) {
    uint32_t a;
    asm("{ .reg .u64 t; cvta.to.shared.u64 t, %1; cvt.u32.u64 %0, t; }" : "=r"(a) : "l"(p));
    return a;
}

// ---------------- small kernels ----------------
__global__ void k_split(const float* __restrict__ Wi, const float* __restrict__ Wii) {
    int i = blockIdx.x * 256 + threadIdx.x;   // 0..262143
    g_wh[i]         = __float2half_rn(Wi[i]);
    g_wh[S * S + i] = __float2half_rn(Wii[i]);
    if (blockIdx.x == 0 && threadIdx.x < B * KF) g_acc[threadIdx.x] = 0.0f;
}

__global__ __launch_bounds__(256)
void k_ln(const float* __restrict__ x,
          const float* __restrict__ ln_g, const float* __restrict__ ln_b,
          const float* __restrict__ w1,   const float* __restrict__ b1,
          const float* __restrict__ wc)
{
    __shared__ float sh[D];
    __shared__ float rsum[8], rsq[8];
    __shared__ float s_mu, s_rs;

    int row = blockIdx.x;
    int b   = row >> 9;
    int s   = row & 511;
    const float* xr = x + (size_t)row * D;
    int t = threadIdx.x;

    float v[6];
    float sum = 0.f, sq = 0.f;
#pragma unroll
    for (int i = 0; i < 6; i++) {
        v[i] = xr[t + 256 * i];
        sum += v[i];
        sq  += v[i] * v[i];
    }
#pragma unroll
    for (int o = 16; o; o >>= 1) {
        sum += __shfl_xor_sync(0xffffffffu, sum, o);
        sq  += __shfl_xor_sync(0xffffffffu, sq,  o);
    }
    if ((t & 31) == 0) { rsum[t >> 5] = sum; rsq[t >> 5] = sq; }
    __syncthreads();
    if (t == 0) {
        float ts = 0.f, tq = 0.f;
#pragma unroll
        for (int i = 0; i < 8; i++) { ts += rsum[i]; tq += rsq[i]; }
        float mu  = ts * (1.0f / D);
        float var = tq * (1.0f / D) - mu * mu;
        s_mu = mu;
        s_rs = rsqrtf(var + 1e-5f);
    }
    __syncthreads();
    float mu = s_mu, rs = s_rs;

    __half* xh = g_xh + (size_t)row * D;
#pragma unroll
    for (int i = 0; i < 6; i++) {
        int idx = t + 256 * i;
        float xn = (v[i] - mu) * rs * ln_g[idx] + ln_b[idx];
        sh[idx] = xn;
        xh[idx] = __float2half_rn(xn);
    }
    __syncthreads();

    if (t < KF) {
        float d = b1[t];
#pragma unroll
        for (int j = 0; j < D24; j++) d += sh[j] * w1[j * KF + t];
        float h = gelu_f(d);
        atomicAdd(&g_acc[b * KF + t], wc[s] * h);
    }
}

__global__ void k_gate(const float* __restrict__ bc,
                       const float* __restrict__ w2,
                       const float* __restrict__ b2)
{
    int b = threadIdx.x;
    if (b < B) {
        float bcv = bc[0];
        float lg = b2[0];
#pragma unroll
        for (int k = 0; k < KF; k++)
            lg += gelu_f(g_acc[b * KF + k] + bcv) * w2[k];
        float g = 1.0f / (1.0f + expf(-lg));
        g_sel[b] = (rintf(g) != 0.0f) ? 1 : 0;
    }
}

// ---------------- HMMA (mma.sync fp16, single term) GEMM ----------------
// Per batch: C[s,d] = sum_t Wsel[s,t] * xn[t,d]; out = gelu(C + bias + residual)
// CTA 128x128, BK=64 (8 chunks), 256 thr / 8 warps, warp tile 64x32, 3-stage cp.async.
#define BM 128
#define BN 128
#define BK 64
#define A_STRIDE 72                      // fp16 per A row (64 + 8 pad) = 144B
#define B_STRIDE 136                     // fp16 per B row (128 + 8 pad) = 272B
#define ABYTES (128 * A_STRIDE * 2)      // 18432
#define BBYTES (64 * B_STRIDE * 2)       // 17408
#define STAGE_BYTES (ABYTES + BBYTES)    // 35840
#define NSTAGE 3
#define SMEM_BYTES (NSTAGE * STAGE_BYTES) // 107520 (epilogue reuse: 128*132*4 = 67584)

#define LDSM_X4(r0, r1, r2, r3, a) \
    asm volatile("ldmatrix.sync.aligned.m8n8.x4.shared.b16 {%0,%1,%2,%3}, [%4];" \
        : "=r"(r0), "=r"(r1), "=r"(r2), "=r"(r3) : "r"(a))
#define LDSM_X4_T(r0, r1, r2, r3, a) \
    asm volatile("ldmatrix.sync.aligned.m8n8.x4.trans.shared.b16 {%0,%1,%2,%3}, [%4];" \
        : "=r"(r0), "=r"(r1), "=r"(r2), "=r"(r3) : "r"(a))
#define MMA16816(c, a, b0, b1) \
    asm volatile("mma.sync.aligned.m16n8k16.row.col.f32.f16.f16.f32 " \
        "{%0,%1,%2,%3}, {%4,%5,%6,%7}, {%8,%9}, {%0,%1,%2,%3};" \
        : "+f"((c)[0]), "+f"((c)[1]), "+f"((c)[2]), "+f"((c)[3]) \
        : "r"((a)[0]), "r"((a)[1]), "r"((a)[2]), "r"((a)[3]), "r"(b0), "r"(b1))
#define CP_ASYNC16(dst, src) \
    asm volatile("cp.async.cg.shared.global [%0], [%1], 16;" :: "r"(dst), "l"(src))

__global__ __launch_bounds__(256, 2)
void k_gemm_mma(const float* __restrict__ bi, const float* __restrict__ bii,
                const float* __restrict__ x,  float* __restrict__ out)
{
    extern __shared__ char smem[];
    uint32_t sb = smem_u32(smem);
    int t = threadIdx.x;
    int lane = t & 31;
    int wid = t >> 5;
    int wm = wid >> 2;        // 0..1 -> m offset wm*64
    int wn = wid & 3;         // 0..3 -> n offset wn*32
    int bb = blockIdx.z;
    int m0 = blockIdx.y * BM;
    int n0 = blockIdx.x * BN;

    int sel = g_sel[bb];
    const __half* wh = g_wh + (size_t)sel * S * S;
    const float* bv = sel ? bii : bi;
    const __half* xh = g_xh + (size_t)bb * S * D;

    // ---- async stage loader (8 x 16B per thread) ----
    auto load_stage = [&](int c, int st) {
        int k0 = c * BK;
        uint32_t base = sb + st * STAGE_BYTES;
#pragma unroll
        for (int i = 0; i < 4; i++) {           // A: 1024 x 16B (128 rows x 8 segs)
            int idx = t + 256 * i;
            int row = idx >> 3, seg = idx & 7;
            const __half* src = wh + (size_t)(m0 + row) * S + k0 + seg * 8;
            uint32_t dst = base + (row * A_STRIDE + seg * 8) * 2;
            CP_ASYNC16(dst, src);
        }
#pragma unroll
        for (int i = 0; i < 4; i++) {           // B: 1024 x 16B (64 rows x 16 segs)
            int idx = t + 256 * i;
            int row = idx >> 4, seg = idx & 15;
            const __half* src = xh + (size_t)(k0 + row) * D + n0 + seg * 8;
            uint32_t dst = base + ABYTES + (row * B_STRIDE + seg * 8) * 2;
            CP_ASYNC16(dst, src);
        }
        asm volatile("cp.async.commit_group;");
    };

    float acc[4][4][4];
#pragma unroll
    for (int i = 0; i < 4; i++)
#pragma unroll
        for (int j = 0; j < 4; j++)
#pragma unroll
            for (int k = 0; k < 4; k++) acc[i][j][k] = 0.f;

    load_stage(0, 0);
    load_stage(1, 1);

    for (int c = 0; c < 8; c++) {
        int st = c % 3;
        if (c < 7) asm volatile("cp.async.wait_group 1;");
        else       asm volatile("cp.async.wait_group 0;");
        __syncthreads();
        if (c + 2 < 8) load_stage(c + 2, (c + 2) % 3);

        uint32_t base = sb + st * STAGE_BYTES;
#pragma unroll
        for (int ks = 0; ks < 4; ks++) {
            int kc = ks * 16 + (lane >> 4) * 8;           // ldmatrix k col
            uint32_t ah[4][4];
#pragma unroll
            for (int mt = 0; mt < 4; mt++) {
                int row = wm * 64 + mt * 16 + (lane & 15);
                uint32_t ad = base + (row * A_STRIDE + kc) * 2;
                LDSM_X4(ah[mt][0], ah[mt][1], ah[mt][2], ah[mt][3], ad);
            }
            uint32_t bh[2][4];
#pragma unroll
            for (int np = 0; np < 2; np++) {
                int krow = ks * 16 + (lane & 15);
                int coln = wn * 32 + np * 16 + (lane >> 4) * 8;
                uint32_t bd = base + ABYTES + (krow * B_STRIDE + coln) * 2;
                LDSM_X4_T(bh[np][0], bh[np][1], bh[np][2], bh[np][3], bd);
            }
#pragma unroll
            for (int mt = 0; mt < 4; mt++)
#pragma unroll
                for (int nt = 0; nt < 4; nt++) {
                    int np = nt >> 1, wq = (nt & 1) * 2;
                    MMA16816(acc[mt][nt], ah[mt], bh[np][wq], bh[np][wq + 1]);
                }
        }
    }
    __syncthreads();

    // ---- epilogue: stage C in SMEM (stride 132 f32), then coalesced out ----
    float* cs = (float*)smem;
#pragma unroll
    for (int mt = 0; mt < 4; mt++)
#pragma unroll
        for (int nt = 0; nt < 4; nt++) {
            int r = wm * 64 + mt * 16 + (lane >> 2);
            int cc = wn * 32 + nt * 8 + (lane & 3) * 2;
            cs[r * 132 + cc]           = acc[mt][nt][0];
            cs[r * 132 + cc + 1]       = acc[mt][nt][1];
            cs[(r + 8) * 132 + cc]     = acc[mt][nt][2];
            cs[(r + 8) * 132 + cc + 1] = acc[mt][nt][3];
        }
    __syncthreads();

#pragma unroll
    for (int i = 0; i < 16; i++) {
        int idx = t + 256 * i;           // 4096 float4s
        int r = idx >> 5, c4 = (idx & 31) * 4;
        float bias = bv[m0 + r];
        size_t off = ((size_t)bb * S + m0 + r) * D + n0 + c4;
        float4 xv = *(const float4*)(x + off);
        float4 ov;
        ov.x = gelu_f(cs[r * 132 + c4 + 0] + bias + xv.x);
        ov.y = gelu_f(cs[r * 132 + c4 + 1] + bias + xv.y);
        ov.z = gelu_f(cs[r * 132 + c4 + 2] + bias + xv.z);
        ov.w = gelu_f(cs[r * 132 + c4 + 3] + bias + xv.w);
        *(float4*)(out + off) = ov;
    }
}

// ---------------- launch ----------------
extern "C" void kernel_launch(void* const* d_in, const int* in_sizes, int n_in,
                              void* d_out, int out_size)
{
    const float* x    = (const float*)d_in[0];
    const float* ln_g = (const float*)d_in[1];
    const float* ln_b = (const float*)d_in[2];
    const float* w1   = (const float*)d_in[3];
    const float* b1   = (const float*)d_in[4];
    const float* wc   = (const float*)d_in[5];
    const float* bc   = (const float*)d_in[6];
    const float* w2   = (const float*)d_in[7];
    const float* b2   = (const float*)d_in[8];
    const float* Wi   = (const float*)d_in[9];
    const float* bi   = (const float*)d_in[10];
    const float* Wii  = (const float*)d_in[11];
    const float* bii  = (const float*)d_in[12];
    float* out = (float*)d_out;

    cudaFuncSetAttribute(k_gemm_mma, cudaFuncAttributeMaxDynamicSharedMemorySize, SMEM_BYTES);

    k_split<<<S * S / 256, 256>>>(Wi, Wii);
    k_ln<<<B * S, 256>>>(x, ln_g, ln_b, w1, b1, wc);
    k_gate<<<1, 32>>>(bc, w2, b2);
    k_gemm_mma<<<dim3(D / BN, S / BM, B), 256, SMEM_BYTES>>>(bi, bii, x, out);
}

// round 15
// speedup vs baseline: 1.1940x; 1.1940x over previous
#include <cuda_runtime.h>
#include <cuda_fp16.h>
#include <math.h>
#include <stdint.h>

#define B 32
#define S 512
#define D 1536
#define D24 64
#define KF 10

// ---------------- device scratch (no allocation allowed) ----------------
__device__ __half g_xh[(size_t)B * S * D];   // xn in fp16
__device__ __half g_wh[2 * S * S];           // W in fp16 (Wi, Wii)
__device__ float g_acc[B * KF];
__device__ int   g_sel[B];
__device__ unsigned int g_done;

__device__ __forceinline__ float gelu_f(float v) {
    return 0.5f * v * (1.0f + erff(v * 0.7071067811865476f));
}
__device__ __forceinline__ uint32_t smem_u32(const void* p) {
    uint32_t a;
    asm("{ .reg .u64 t; cvta.to.shared.u64 t, %1; cvt.u32.u64 %0, t; }" : "=r"(a) : "l"(p));
    return a;
}

// ---------------- W convert + state reset ----------------
__global__ void k_split(const float* __restrict__ Wi, const float* __restrict__ Wii) {
    int i = blockIdx.x * 256 + threadIdx.x;   // 0..262143
    g_wh[i]         = __float2half_rn(Wi[i]);
    g_wh[S * S + i] = __float2half_rn(Wii[i]);
    if (blockIdx.x == 0) {
        if (threadIdx.x < B * KF) g_acc[threadIdx.x] = 0.0f;
        if (threadIdx.x == 0) g_done = 0u;
    }
}

// ---------------- LayerNorm + gating features + fused gate decision ----------------
__global__ __launch_bounds__(256)
void k_ln(const float* __restrict__ x,
          const float* __restrict__ ln_g, const float* __restrict__ ln_b,
          const float* __restrict__ w1,   const float* __restrict__ b1,
          const float* __restrict__ wc,   const float* __restrict__ bc,
          const float* __restrict__ w2,   const float* __restrict__ b2)
{
    __shared__ float sh[D];
    __shared__ float rsum[8], rsq[8];
    __shared__ float s_mu, s_rs;

    int row = blockIdx.x;
    int b   = row >> 9;
    int s   = row & 511;
    const float* xr = x + (size_t)row * D;
    int t = threadIdx.x;

    float v[6];
    float sum = 0.f, sq = 0.f;
#pragma unroll
    for (int i = 0; i < 6; i++) {
        v[i] = xr[t + 256 * i];
        sum += v[i];
        sq  += v[i] * v[i];
    }
#pragma unroll
    for (int o = 16; o; o >>= 1) {
        sum += __shfl_xor_sync(0xffffffffu, sum, o);
        sq  += __shfl_xor_sync(0xffffffffu, sq,  o);
    }
    if ((t & 31) == 0) { rsum[t >> 5] = sum; rsq[t >> 5] = sq; }
    __syncthreads();
    if (t == 0) {
        float ts = 0.f, tq = 0.f;
#pragma unroll
        for (int i = 0; i < 8; i++) { ts += rsum[i]; tq += rsq[i]; }
        float mu  = ts * (1.0f / D);
        float var = tq * (1.0f / D) - mu * mu;
        s_mu = mu;
        s_rs = rsqrtf(var + 1e-5f);
    }
    __syncthreads();
    float mu = s_mu, rs = s_rs;

    __half* xh = g_xh + (size_t)row * D;
#pragma unroll
    for (int i = 0; i < 6; i++) {
        int idx = t + 256 * i;
        float xn = (v[i] - mu) * rs * ln_g[idx] + ln_b[idx];
        sh[idx] = xn;
        xh[idx] = __float2half_rn(xn);
    }
    __syncthreads();

    if (t < KF) {
        float d = b1[t];
#pragma unroll
        for (int j = 0; j < D24; j++) d += sh[j] * w1[j * KF + t];
        float h = gelu_f(d);
        atomicAdd(&g_acc[b * KF + t], wc[s] * h);
    }
    __syncthreads();

    // last block to finish computes the per-batch gate (kills k_gate launch)
    if (t == 0) {
        __threadfence();
        unsigned int old = atomicAdd(&g_done, 1u);
        if (old == (unsigned int)(B * S - 1)) {
            __threadfence();
            float bcv = bc[0];
            float b2v = b2[0];
            for (int bq = 0; bq < B; bq++) {
                float lg = b2v;
#pragma unroll
                for (int k = 0; k < KF; k++)
                    lg += gelu_f(g_acc[bq * KF + k] + bcv) * w2[k];
                float g = 1.0f / (1.0f + expf(-lg));
                g_sel[bq] = (rintf(g) != 0.0f) ? 1 : 0;
            }
            __threadfence();
        }
    }
}

// ---------------- HMMA (mma.sync fp16, single term) GEMM ----------------
// Per batch: C[s,d] = sum_t Wsel[s,t] * xn[t,d]; out = gelu(C + bias + residual)
// CTA 128x128, BK=32 (16 chunks), 256 thr / 8 warps, warp tile 64x32, 5-stage cp.async.
#define BM 128
#define BN 128
#define BK 32
#define A_STRIDE 40                      // fp16 per A row (32 + 8 pad) = 80B
#define B_STRIDE 136                     // fp16 per B row (128 + 8 pad) = 272B
#define ABYTES (128 * A_STRIDE * 2)      // 10240
#define BBYTES (32 * B_STRIDE * 2)       // 8704
#define STAGE_BYTES (ABYTES + BBYTES)    // 18944
#define NSTAGE 5
#define SMEM_BYTES (NSTAGE * STAGE_BYTES) // 94720 (epilogue reuse: 128*132*4 = 67584)

#define LDSM_X4(r0, r1, r2, r3, a) \
    asm volatile("ldmatrix.sync.aligned.m8n8.x4.shared.b16 {%0,%1,%2,%3}, [%4];" \
        : "=r"(r0), "=r"(r1), "=r"(r2), "=r"(r3) : "r"(a))
#define LDSM_X4_T(r0, r1, r2, r3, a) \
    asm volatile("ldmatrix.sync.aligned.m8n8.x4.trans.shared.b16 {%0,%1,%2,%3}, [%4];" \
        : "=r"(r0), "=r"(r1), "=r"(r2), "=r"(r3) : "r"(a))
#define MMA16816(c, a, b0, b1) \
    asm volatile("mma.sync.aligned.m16n8k16.row.col.f32.f16.f16.f32 " \
        "{%0,%1,%2,%3}, {%4,%5,%6,%7}, {%8,%9}, {%0,%1,%2,%3};" \
        : "+f"((c)[0]), "+f"((c)[1]), "+f"((c)[2]), "+f"((c)[3]) \
        : "r"((a)[0]), "r"((a)[1]), "r"((a)[2]), "r"((a)[3]), "r"(b0), "r"(b1))
#define CP_ASYNC16(dst, src) \
    asm volatile("cp.async.cg.shared.global [%0], [%1], 16;" :: "r"(dst), "l"(src))

__global__ __launch_bounds__(256, 2)
void k_gemm_mma(const float* __restrict__ bi, const float* __restrict__ bii,
                const float* __restrict__ x,  float* __restrict__ out)
{
    extern __shared__ char smem[];
    uint32_t sb = smem_u32(smem);
    int t = threadIdx.x;
    int lane = t & 31;
    int wid = t >> 5;
    int wm = wid >> 2;        // 0..1 -> m offset wm*64
    int wn = wid & 3;         // 0..3 -> n offset wn*32
    int bb = blockIdx.z;
    int m0 = blockIdx.y * BM;
    int n0 = blockIdx.x * BN;

    int sel = g_sel[bb];
    const __half* wh = g_wh + (size_t)sel * S * S;
    const float* bv = sel ? bii : bi;
    const __half* xh = g_xh + (size_t)bb * S * D;

    // ---- async stage loader (4 x 16B per thread) ----
    auto load_stage = [&](int c, int st) {
        int k0 = c * BK;
        uint32_t base = sb + st * STAGE_BYTES;
#pragma unroll
        for (int i = 0; i < 2; i++) {           // A: 512 x 16B
            int idx = t + 256 * i;
            int row = idx >> 2, seg = idx & 3;
            const __half* src = wh + (size_t)(m0 + row) * S + k0 + seg * 8;
            uint32_t dst = base + (row * A_STRIDE + seg * 8) * 2;
            CP_ASYNC16(dst, src);
        }
#pragma unroll
        for (int i = 0; i < 2; i++) {           // B: 512 x 16B
            int idx = t + 256 * i;
            int row = idx >> 4, seg = idx & 15;
            const __half* src = xh + (size_t)(k0 + row) * D + n0 + seg * 8;
            uint32_t dst = base + ABYTES + (row * B_STRIDE + seg * 8) * 2;
            CP_ASYNC16(dst, src);
        }
        asm volatile("cp.async.commit_group;");
    };

    float acc[4][4][4];
#pragma unroll
    for (int i = 0; i < 4; i++)
#pragma unroll
        for (int j = 0; j < 4; j++)
#pragma unroll
            for (int k = 0; k < 4; k++) acc[i][j][k] = 0.f;

    load_stage(0, 0);
    load_stage(1, 1);
    load_stage(2, 2);
    load_stage(3, 3);

    for (int c = 0; c < 16; c++) {
        int st = c % NSTAGE;
        // ensure group c complete; keep up to min(3, 15-c) newer groups in flight
        if (c <= 12)      asm volatile("cp.async.wait_group 3;");
        else if (c == 13) asm volatile("cp.async.wait_group 2;");
        else if (c == 14) asm volatile("cp.async.wait_group 1;");
        else              asm volatile("cp.async.wait_group 0;");
        __syncthreads();
        if (c + 4 < 16) load_stage(c + 4, (c + 4) % NSTAGE);

        uint32_t base = sb + st * STAGE_BYTES;
#pragma unroll
        for (int ks = 0; ks < 2; ks++) {
            int kc = ks * 16 + (lane >> 4) * 8;           // ldmatrix k col
            uint32_t ah[4][4];
#pragma unroll
            for (int mt = 0; mt < 4; mt++) {
                int row = wm * 64 + mt * 16 + (lane & 15);
                uint32_t ad = base + (row * A_STRIDE + kc) * 2;
                LDSM_X4(ah[mt][0], ah[mt][1], ah[mt][2], ah[mt][3], ad);
            }
            uint32_t bh[2][4];
#pragma unroll
            for (int np = 0; np < 2; np++) {
                int krow = ks * 16 + (lane & 15);
                int coln = wn * 32 + np * 16 + (lane >> 4) * 8;
                uint32_t bd = base + ABYTES + (krow * B_STRIDE + coln) * 2;
                LDSM_X4_T(bh[np][0], bh[np][1], bh[np][2], bh[np][3], bd);
            }
#pragma unroll
            for (int mt = 0; mt < 4; mt++)
#pragma unroll
                for (int nt = 0; nt < 4; nt++) {
                    int np = nt >> 1, wq = (nt & 1) * 2;
                    MMA16816(acc[mt][nt], ah[mt], bh[np][wq], bh[np][wq + 1]);
                }
        }
    }
    __syncthreads();

    // ---- epilogue: stage C in SMEM (stride 132 f32), then coalesced out ----
    float* cs = (float*)smem;
#pragma unroll
    for (int mt = 0; mt < 4; mt++)
#pragma unroll
        for (int nt = 0; nt < 4; nt++) {
            int r = wm * 64 + mt * 16 + (lane >> 2);
            int cc = wn * 32 + nt * 8 + (lane & 3) * 2;
            cs[r * 132 + cc]           = acc[mt][nt][0];
            cs[r * 132 + cc + 1]       = acc[mt][nt][1];
            cs[(r + 8) * 132 + cc]     = acc[mt][nt][2];
            cs[(r + 8) * 132 + cc + 1] = acc[mt][nt][3];
        }
    __syncthreads();

#pragma unroll
    for (int i = 0; i < 16; i++) {
        int idx = t + 256 * i;           // 4096 float4s
        int r = idx >> 5, c4 = (idx & 31) * 4;
        float bias = bv[m0 + r];
        size_t off = ((size_t)bb * S + m0 + r) * D + n0 + c4;
        float4 xv = *(const float4*)(x + off);
        float4 ov;
        ov.x = gelu_f(cs[r * 132 + c4 + 0] + bias + xv.x);
        ov.y = gelu_f(cs[r * 132 + c4 + 1] + bias + xv.y);
        ov.z = gelu_f(cs[r * 132 + c4 + 2] + bias + xv.z);
        ov.w = gelu_f(cs[r * 132 + c4 + 3] + bias + xv.w);
        *(float4*)(out + off) = ov;
    }
}

// ---------------- launch ----------------
extern "C" void kernel_launch(void* const* d_in, const int* in_sizes, int n_in,
                              void* d_out, int out_size)
{
    const float* x    = (const float*)d_in[0];
    const float* ln_g = (const float*)d_in[1];
    const float* ln_b = (const float*)d_in[2];
    const float* w1   = (const float*)d_in[3];
    const float* b1   = (const float*)d_in[4];
    const float* wc   = (const float*)d_in[5];
    const float* bc   = (const float*)d_in[6];
    const float* w2   = (const float*)d_in[7];
    const float* b2   = (const float*)d_in[8];
    const float* Wi   = (const float*)d_in[9];
    const float* bi   = (const float*)d_in[10];
    const float* Wii  = (const float*)d_in[11];
    const float* bii  = (const float*)d_in[12];
    float* out = (float*)d_out;

    cudaFuncSetAttribute(k_gemm_mma, cudaFuncAttributeMaxDynamicSharedMemorySize, SMEM_BYTES);

    k_split<<<S * S / 256, 256>>>(Wi, Wii);
    k_ln<<<B * S, 256>>>(x, ln_g, ln_b, w1, b1, wc, bc, w2, b2);
    k_gemm_mma<<<dim3(D / BN, S / BM, B), 256, SMEM_BYTES>>>(bi, bii, x, out);
}

// round 17
// speedup vs baseline: 1.3624x; 1.1410x over previous
#include <cuda_runtime.h>
#include <cuda_fp16.h>
#include <math.h>
#include <stdint.h>

#define B 32
#define S 512
#define D 1536
#define D24 64
#define KF 10

// ---------------- device scratch (no allocation allowed) ----------------
__device__ __half g_xh[(size_t)B * S * D];   // xn in fp16
__device__ __half g_wh[2 * S * S];           // W in fp16 (Wi, Wii)
__device__ float g_acc[B * KF];
__device__ int   g_sel[B];
__device__ unsigned int g_done;

__device__ __forceinline__ float gelu_f(float v) {
    return 0.5f * v * (1.0f + erff(v * 0.7071067811865476f));
}
__device__ __forceinline__ uint32_t smem_u32(const void* p) {
    uint32_t a;
    asm("{ .reg .u64 t; cvta.to.shared.u64 t, %1; cvt.u32.u64 %0, t; }" : "=r"(a) : "l"(p));
    return a;
}

// ---------------- W convert + state reset ----------------
__global__ void k_split(const float* __restrict__ Wi, const float* __restrict__ Wii) {
    int i = blockIdx.x * 256 + threadIdx.x;   // 0..262143
    g_wh[i]         = __float2half_rn(Wi[i]);
    g_wh[S * S + i] = __float2half_rn(Wii[i]);
    if (blockIdx.x == 0) {
        if (threadIdx.x < B * KF) g_acc[threadIdx.x] = 0.0f;
        if (threadIdx.x == 0) g_done = 0u;
    }
}

// ---------------- LayerNorm (2 rows/block, float4) + gating + parallel gate ----------------
__global__ __launch_bounds__(256)
void k_ln(const float* __restrict__ x,
          const float* __restrict__ ln_g, const float* __restrict__ ln_b,
          const float* __restrict__ w1,   const float* __restrict__ b1,
          const float* __restrict__ wc,   const float* __restrict__ bc,
          const float* __restrict__ w2,   const float* __restrict__ b2)
{
    __shared__ float rsum[8], rsq[8];
    __shared__ float s_mu[2], s_rs[2];
    __shared__ float sg[2][64];
    __shared__ int s_last;

    int t = threadIdx.x;
    int half = t >> 7;            // 0/1 -> which row of the pair
    int j = t & 127;              // lane within row
    int row = blockIdx.x * 2 + half;
    int b = row >> 9, s = row & 511;

    const float4* xr4 = (const float4*)(x + (size_t)row * D);
    float4 v[3];
    float sum = 0.f, sq = 0.f;
#pragma unroll
    for (int i = 0; i < 3; i++) {
        v[i] = xr4[j + 128 * i];
        sum += v[i].x + v[i].y + v[i].z + v[i].w;
        sq  += v[i].x * v[i].x + v[i].y * v[i].y + v[i].z * v[i].z + v[i].w * v[i].w;
    }
#pragma unroll
    for (int o = 16; o; o >>= 1) {
        sum += __shfl_xor_sync(0xffffffffu, sum, o);
        sq  += __shfl_xor_sync(0xffffffffu, sq,  o);
    }
    if ((t & 31) == 0) { rsum[t >> 5] = sum; rsq[t >> 5] = sq; }
    __syncthreads();
    if (j == 0) {
        float ts = 0.f, tq = 0.f;
#pragma unroll
        for (int i = 0; i < 4; i++) { ts += rsum[half * 4 + i]; tq += rsq[half * 4 + i]; }
        float mu  = ts * (1.0f / D);
        float var = tq * (1.0f / D) - mu * mu;
        s_mu[half] = mu;
        s_rs[half] = rsqrtf(var + 1e-5f);
    }
    __syncthreads();
    float mu = s_mu[half], rs = s_rs[half];

    const float4* g4 = (const float4*)ln_g;
    const float4* b4 = (const float4*)ln_b;
    __half2* xh2 = (__half2*)(g_xh + (size_t)row * D);
#pragma unroll
    for (int i = 0; i < 3; i++) {
        int idx = j + 128 * i;                // float4 index within row
        float4 gv = g4[idx], bv = b4[idx];
        float4 xn;
        xn.x = (v[i].x - mu) * rs * gv.x + bv.x;
        xn.y = (v[i].y - mu) * rs * gv.y + bv.y;
        xn.z = (v[i].z - mu) * rs * gv.z + bv.z;
        xn.w = (v[i].w - mu) * rs * gv.w + bv.w;
        xh2[idx * 2]     = __floats2half2_rn(xn.x, xn.y);
        xh2[idx * 2 + 1] = __floats2half2_rn(xn.z, xn.w);
        if (i == 0 && j < 16) {               // dims 0..63 feed the gate
            sg[half][j * 4 + 0] = xn.x;
            sg[half][j * 4 + 1] = xn.y;
            sg[half][j * 4 + 2] = xn.z;
            sg[half][j * 4 + 3] = xn.w;
        }
    }
    __syncthreads();

    if (j < KF) {
        float d = b1[j];
#pragma unroll
        for (int q = 0; q < D24; q++) d += sg[half][q] * w1[q * KF + j];
        atomicAdd(&g_acc[b * KF + j], wc[s] * gelu_f(d));
    }
    __syncthreads();

    // last block computes all 32 gates, parallel across threads
    if (t == 0) {
        __threadfence();
        unsigned int old = atomicAdd(&g_done, 1u);
        s_last = (old == (unsigned int)(B * S / 2 - 1)) ? 1 : 0;
    }
    __syncthreads();
    if (s_last) {
        __threadfence();
        if (t < B) {
            float bcv = bc[0];
            float lg = b2[0];
#pragma unroll
            for (int k = 0; k < KF; k++)
                lg += gelu_f(g_acc[t * KF + k] + bcv) * w2[k];
            float g = 1.0f / (1.0f + expf(-lg));
            g_sel[t] = (rintf(g) != 0.0f) ? 1 : 0;
        }
        __threadfence();
    }
}

// ---------------- HMMA (mma.sync fp16, single term) GEMM — exact R10 config ----------------
// Per batch: C[s,d] = sum_t Wsel[s,t] * xn[t,d]; out = gelu(C + bias + residual)
// CTA 128x128, BK=32 (16 chunks), 256 thr / 8 warps, warp tile 64x32, 4-stage cp.async.
#define BM 128
#define BN 128
#define BK 32
#define A_STRIDE 40                      // fp16 per A row (32 + 8 pad) = 80B
#define B_STRIDE 136                     // fp16 per B row (128 + 8 pad) = 272B
#define ABYTES (128 * A_STRIDE * 2)      // 10240
#define BBYTES (32 * B_STRIDE * 2)       // 8704
#define STAGE_BYTES (ABYTES + BBYTES)    // 18944
#define NSTAGE 4
#define SMEM_BYTES (NSTAGE * STAGE_BYTES) // 75776 (epilogue reuse: 128*132*4 = 67584)

#define LDSM_X4(r0, r1, r2, r3, a) \
    asm volatile("ldmatrix.sync.aligned.m8n8.x4.shared.b16 {%0,%1,%2,%3}, [%4];" \
        : "=r"(r0), "=r"(r1), "=r"(r2), "=r"(r3) : "r"(a))
#define LDSM_X4_T(r0, r1, r2, r3, a) \
    asm volatile("ldmatrix.sync.aligned.m8n8.x4.trans.shared.b16 {%0,%1,%2,%3}, [%4];" \
        : "=r"(r0), "=r"(r1), "=r"(r2), "=r"(r3) : "r"(a))
#define MMA16816(c, a, b0, b1) \
    asm volatile("mma.sync.aligned.m16n8k16.row.col.f32.f16.f16.f32 " \
        "{%0,%1,%2,%3}, {%4,%5,%6,%7}, {%8,%9}, {%0,%1,%2,%3};" \
        : "+f"((c)[0]), "+f"((c)[1]), "+f"((c)[2]), "+f"((c)[3]) \
        : "r"((a)[0]), "r"((a)[1]), "r"((a)[2]), "r"((a)[3]), "r"(b0), "r"(b1))
#define CP_ASYNC16(dst, src) \
    asm volatile("cp.async.cg.shared.global [%0], [%1], 16;" :: "r"(dst), "l"(src))

__global__ __launch_bounds__(256, 2)
void k_gemm_mma(const float* __restrict__ bi, const float* __restrict__ bii,
                const float* __restrict__ x,  float* __restrict__ out)
{
    extern __shared__ char smem[];
    uint32_t sb = smem_u32(smem);
    int t = threadIdx.x;
    int lane = t & 31;
    int wid = t >> 5;
    int wm = wid >> 2;        // 0..1 -> m offset wm*64
    int wn = wid & 3;         // 0..3 -> n offset wn*32
    int bb = blockIdx.z;
    int m0 = blockIdx.y * BM;
    int n0 = blockIdx.x * BN;

    int sel = g_sel[bb];
    const __half* wh = g_wh + (size_t)sel * S * S;
    const float* bv = sel ? bii : bi;
    const __half* xh = g_xh + (size_t)bb * S * D;

    // ---- async stage loader (4 x 16B per thread) ----
    auto load_stage = [&](int c, int st) {
        int k0 = c * BK;
        uint32_t base = sb + st * STAGE_BYTES;
#pragma unroll
        for (int i = 0; i < 2; i++) {           // A: 512 x 16B
            int idx = t + 256 * i;
            int row = idx >> 2, seg = idx & 3;
            const __half* src = wh + (size_t)(m0 + row) * S + k0 + seg * 8;
            uint32_t dst = base + (row * A_STRIDE + seg * 8) * 2;
            CP_ASYNC16(dst, src);
        }
#pragma unroll
        for (int i = 0; i < 2; i++) {           // B: 512 x 16B
            int idx = t + 256 * i;
            int row = idx >> 4, seg = idx & 15;
            const __half* src = xh + (size_t)(k0 + row) * D + n0 + seg * 8;
            uint32_t dst = base + ABYTES + (row * B_STRIDE + seg * 8) * 2;
            CP_ASYNC16(dst, src);
        }
        asm volatile("cp.async.commit_group;");
    };

    float acc[4][4][4];
#pragma unroll
    for (int i = 0; i < 4; i++)
#pragma unroll
        for (int j = 0; j < 4; j++)
#pragma unroll
            for (int k = 0; k < 4; k++) acc[i][j][k] = 0.f;

    load_stage(0, 0);
    load_stage(1, 1);
    load_stage(2, 2);

    for (int c = 0; c < 16; c++) {
        int st = c & 3;
        // drain so stage c is complete; keep up to 2 newer groups in flight
        if (c < 14)       asm volatile("cp.async.wait_group 2;");
        else if (c == 14) asm volatile("cp.async.wait_group 1;");
        else              asm volatile("cp.async.wait_group 0;");
        __syncthreads();
        if (c + 3 < 16) load_stage(c + 3, (c + 3) & 3);

        uint32_t base = sb + st * STAGE_BYTES;
#pragma unroll
        for (int ks = 0; ks < 2; ks++) {
            int kc = ks * 16 + (lane >> 4) * 8;           // ldmatrix k col
            uint32_t ah[4][4];
#pragma unroll
            for (int mt = 0; mt < 4; mt++) {
                int row = wm * 64 + mt * 16 + (lane & 15);
                uint32_t ad = base + (row * A_STRIDE + kc) * 2;
                LDSM_X4(ah[mt][0], ah[mt][1], ah[mt][2], ah[mt][3], ad);
            }
            uint32_t bh[2][4];
#pragma unroll
            for (int np = 0; np < 2; np++) {
                int krow = ks * 16 + (lane & 15);
                int coln = wn * 32 + np * 16 + (lane >> 4) * 8;
                uint32_t bd = base + ABYTES + (krow * B_STRIDE + coln) * 2;
                LDSM_X4_T(bh[np][0], bh[np][1], bh[np][2], bh[np][3], bd);
            }
#pragma unroll
            for (int mt = 0; mt < 4; mt++)
#pragma unroll
                for (int nt = 0; nt < 4; nt++) {
                    int np = nt >> 1, wq = (nt & 1) * 2;
                    MMA16816(acc[mt][nt], ah[mt], bh[np][wq], bh[np][wq + 1]);
                }
        }
    }
    __syncthreads();

    // ---- epilogue: stage C in SMEM (stride 132 f32), then coalesced out ----
    float* cs = (float*)smem;
#pragma unroll
    for (int mt = 0; mt < 4; mt++)
#pragma unroll
        for (int nt = 0; nt < 4; nt++) {
            int r = wm * 64 + mt * 16 + (lane >> 2);
            int cc = wn * 32 + nt * 8 + (lane & 3) * 2;
            cs[r * 132 + cc]           = acc[mt][nt][0];
            cs[r * 132 + cc + 1]       = acc[mt][nt][1];
            cs[(r + 8) * 132 + cc]     = acc[mt][nt][2];
            cs[(r + 8) * 132 + cc + 1] = acc[mt][nt][3];
        }
    __syncthreads();

#pragma unroll
    for (int i = 0; i < 16; i++) {
        int idx = t + 256 * i;           // 4096 float4s
        int r = idx >> 5, c4 = (idx & 31) * 4;
        float bias = bv[m0 + r];
        size_t off = ((size_t)bb * S + m0 + r) * D + n0 + c4;
        float4 xv = *(const float4*)(x + off);
        float4 ov;
        ov.x = gelu_f(cs[r * 132 + c4 + 0] + bias + xv.x);
        ov.y = gelu_f(cs[r * 132 + c4 + 1] + bias + xv.y);
        ov.z = gelu_f(cs[r * 132 + c4 + 2] + bias + xv.z);
        ov.w = gelu_f(cs[r * 132 + c4 + 3] + bias + xv.w);
        *(float4*)(out + off) = ov;
    }
}

// ---------------- launch ----------------
extern "C" void kernel_launch(void* const* d_in, const int* in_sizes, int n_in,
                              void* d_out, int out_size)
{
    const float* x    = (const float*)d_in[0];
    const float* ln_g = (const float*)d_in[1];
    const float* ln_b = (const float*)d_in[2];
    const float* w1   = (const float*)d_in[3];
    const float* b1   = (const float*)d_in[4];
    const float* wc   = (const float*)d_in[5];
    const float* bc   = (const float*)d_in[6];
    const float* w2   = (const float*)d_in[7];
    const float* b2   = (const float*)d_in[8];
    const float* Wi   = (const float*)d_in[9];
    const float* bi   = (const float*)d_in[10];
    const float* Wii  = (const float*)d_in[11];
    const float* bii  = (const float*)d_in[12];
    float* out = (float*)d_out;

    cudaFuncSetAttribute(k_gemm_mma, cudaFuncAttributeMaxDynamicSharedMemorySize, SMEM_BYTES);

    k_split<<<S * S / 256, 256>>>(Wi, Wii);
    k_ln<<<B * S / 2, 256>>>(x, ln_g, ln_b, w1, b1, wc, bc, w2, b2);
    k_gemm_mma<<<dim3(D / BN, S / BM, B), 256, SMEM_BYTES>>>(bi, bii, x, out);
}